// round 4
// baseline (speedup 1.0000x reference)
#include <cuda_runtime.h>
#include <cuda_bf16.h>
#include <math.h>

// ---------------- problem constants ----------------
#define NN   20000
#define FF   128
#define HH   8
#define EE   200000
#define PTSN 4
#define EEE  (EE+NN)
#define NCLSC 133

// ---------------- scratch (device globals; aliased where lifetimes allow) ---
// pool A: xl1 during layer 1 (dead after layer-1 aggregate), finalh at the end
__device__ float    g_poolA[NN*512];
__device__ float    g_s1[NN*HH];
__device__ float    g_d1[NN*HH];
__device__ unsigned g_amax1[NN*HH];
__device__ float    g_den1[NN*HH];
__device__ float    g_alpha1[(size_t)EEE*HH];
__device__ float    g_out1[NN*512];
__device__ float    g_xl2[NN*512];
__device__ float    g_s2[NN];
__device__ float    g_d2[NN];
__device__ unsigned g_amax2[NN];
__device__ float    g_den2[NN];
__device__ float    g_alpha2[EEE];
__device__ float    g_out2[NN*512];
__device__ float    g_xp6[EE*6];
__device__ float    g_leftsum[NN*512];
__device__ float    g_rightsum[NN*512];
__device__ float    g_invL[NN];
__device__ float    g_invR[NN];
__device__ float    g_cntL[NN];
__device__ float    g_cntR[NN];

// ---------------- helpers ----------------
__device__ __forceinline__ unsigned enc_f(float f) {
    unsigned u = __float_as_uint(f);
    return (u & 0x80000000u) ? ~u : (u | 0x80000000u);
}
__device__ __forceinline__ float dec_f(unsigned u) {
    return (u & 0x80000000u) ? __uint_as_float(u & 0x7FFFFFFFu)
                             : __uint_as_float(~u);
}
__device__ __forceinline__ void edsd(const int* __restrict__ ei, int e, int& s, int& d) {
    if (e < EE) { s = ei[e]; d = ei[EE + e]; }
    else        { s = d = e - EE; }
}

// ---------------- zero/init ----------------
__global__ void zero_kernel() {
    int i = blockIdx.x * blockDim.x + threadIdx.x;
    if (i < NN*512) {
        g_out1[i] = 0.f; g_out2[i] = 0.f;
        g_leftsum[i] = 0.f; g_rightsum[i] = 0.f;
    }
    if (i < NN*HH) { g_amax1[i] = 0u; g_den1[i] = 0.f; }
    if (i < NN)    { g_amax2[i] = 0u; g_den2[i] = 0.f; g_cntL[i] = 0.f; g_cntR[i] = 0.f; }
}

// ---------------- generic tiled fp32 GEMM ----------------
template<int ACT>
__global__ __launch_bounds__(256)
void gemm64(const float* __restrict__ A, const float* __restrict__ B,
            const float* __restrict__ bias, float* __restrict__ C,
            int M, int Nc, int K)
{
    __shared__ float As[16][65];
    __shared__ float Bs[16][65];
    int tid = threadIdx.x;
    int tx = tid & 15, ty = tid >> 4;
    int row0 = blockIdx.y * 64, col0 = blockIdx.x * 64;
    float acc[4][4] = {};
    for (int k0 = 0; k0 < K; k0 += 16) {
        #pragma unroll
        for (int i = 0; i < 4; i++) {
            int idx = tid + i * 256;
            int m = idx >> 4, kk = idx & 15;
            int gr = row0 + m;
            As[kk][m] = (gr < M) ? A[(size_t)gr * K + k0 + kk] : 0.f;
        }
        #pragma unroll
        for (int i = 0; i < 4; i++) {
            int idx = tid + i * 256;
            int kk = idx >> 6, n = idx & 63;
            int gc = col0 + n;
            Bs[kk][n] = (gc < Nc) ? B[(size_t)(k0 + kk) * Nc + gc] : 0.f;
        }
        __syncthreads();
        #pragma unroll
        for (int kk = 0; kk < 16; kk++) {
            float a[4], b[4];
            #pragma unroll
            for (int i = 0; i < 4; i++) a[i] = As[kk][ty + 16*i];
            #pragma unroll
            for (int j = 0; j < 4; j++) b[j] = Bs[kk][tx + 16*j];
            #pragma unroll
            for (int i = 0; i < 4; i++)
                #pragma unroll
                for (int j = 0; j < 4; j++) acc[i][j] += a[i] * b[j];
        }
        __syncthreads();
    }
    #pragma unroll
    for (int i = 0; i < 4; i++) {
        int r = row0 + ty + 16*i;
        if (r >= M) continue;
        #pragma unroll
        for (int j = 0; j < 4; j++) {
            int c = col0 + tx + 16*j;
            if (c >= Nc) continue;
            float v = acc[i][j];
            if (bias) v += bias[c];
            if (ACT == 1) v = fmaxf(v, 0.f);
            C[(size_t)r * Nc + c] = v;
        }
    }
}

// ---- fused edge branch: A = relu(xp6 @ We1 + be1) on the fly;
//      (A @ We2 + be2) scattered into leftsum[src]/rightsum[dst]
__global__ __launch_bounds__(256)
void edge_gemm_scatter(const float* __restrict__ We1, const float* __restrict__ be1,
                       const float* __restrict__ We2, const float* __restrict__ be2,
                       const int* __restrict__ ei)
{
    __shared__ float As[16][65];
    __shared__ float Bs[16][65];
    __shared__ float Xs[64][6];
    int tid = threadIdx.x;
    int tx = tid & 15, ty = tid >> 4;
    int row0 = blockIdx.y * 64, col0 = blockIdx.x * 64;

    // stage xp6 rows for this block (64 rows x 6 = 384 entries, 256 threads)
    for (int idx = tid; idx < 64 * 6; idx += 256) {
        int m = idx / 6, j = idx % 6;
        int gr = row0 + m;
        Xs[m][j] = (gr < EE) ? g_xp6[(size_t)gr * 6 + j] : 0.f;
    }
    __syncthreads();

    float acc[4][4] = {};
    for (int k0 = 0; k0 < 256; k0 += 16) {
        #pragma unroll
        for (int i = 0; i < 4; i++) {
            int idx = tid + i * 256;
            int m = idx >> 4, kk = idx & 15;
            int gk = k0 + kk;
            float v = be1[gk];
            #pragma unroll
            for (int j = 0; j < 6; j++) v += Xs[m][j] * We1[j * 256 + gk];
            As[kk][m] = fmaxf(v, 0.f);
        }
        #pragma unroll
        for (int i = 0; i < 4; i++) {
            int idx = tid + i * 256;
            int kk = idx >> 6, n = idx & 63;
            Bs[kk][n] = We2[(size_t)(k0 + kk) * 512 + col0 + n];
        }
        __syncthreads();
        #pragma unroll
        for (int kk = 0; kk < 16; kk++) {
            float a[4], b[4];
            #pragma unroll
            for (int i = 0; i < 4; i++) a[i] = As[kk][ty + 16*i];
            #pragma unroll
            for (int j = 0; j < 4; j++) b[j] = Bs[kk][tx + 16*j];
            #pragma unroll
            for (int i = 0; i < 4; i++)
                #pragma unroll
                for (int j = 0; j < 4; j++) acc[i][j] += a[i] * b[j];
        }
        __syncthreads();
    }
    #pragma unroll
    for (int i = 0; i < 4; i++) {
        int r = row0 + ty + 16*i;
        if (r >= EE) continue;
        int s = ei[r], d = ei[EE + r];
        #pragma unroll
        for (int j = 0; j < 4; j++) {
            int c = col0 + tx + 16*j;
            float v = acc[i][j] + be2[c];
            atomicAdd(&g_leftsum [(size_t)s * 512 + c], v);
            atomicAdd(&g_rightsum[(size_t)d * 512 + c], v);
        }
    }
}

// ---- classifier GEMM; A = [out2+b2 | left*invL | right*invR] assembled on the fly
__global__ __launch_bounds__(256)
void gemm64_final(const float* __restrict__ b2, const float* __restrict__ Wc1,
                  const float* __restrict__ bc1, float* __restrict__ C)
{
    __shared__ float As[16][65];
    __shared__ float Bs[16][65];
    int tid = threadIdx.x;
    int tx = tid & 15, ty = tid >> 4;
    int row0 = blockIdx.y * 64, col0 = blockIdx.x * 64;
    float acc[4][4] = {};
    for (int k0 = 0; k0 < 1536; k0 += 16) {
        #pragma unroll
        for (int i = 0; i < 4; i++) {
            int idx = tid + i * 256;
            int m = idx >> 4, kk = idx & 15;
            int gr = row0 + m, gk = k0 + kk;
            float v = 0.f;
            if (gr < NN) {
                if (gk < 512)        v = g_out2[(size_t)gr * 512 + gk] + b2[gk];
                else if (gk < 1024)  v = g_leftsum [(size_t)gr * 512 + (gk - 512)]  * g_invL[gr];
                else                 v = g_rightsum[(size_t)gr * 512 + (gk - 1024)] * g_invR[gr];
            }
            As[kk][m] = v;
        }
        #pragma unroll
        for (int i = 0; i < 4; i++) {
            int idx = tid + i * 256;
            int kk = idx >> 6, n = idx & 63;
            Bs[kk][n] = Wc1[(size_t)(k0 + kk) * 512 + col0 + n];
        }
        __syncthreads();
        #pragma unroll
        for (int kk = 0; kk < 16; kk++) {
            float a[4], b[4];
            #pragma unroll
            for (int i = 0; i < 4; i++) a[i] = As[kk][ty + 16*i];
            #pragma unroll
            for (int j = 0; j < 4; j++) b[j] = Bs[kk][tx + 16*j];
            #pragma unroll
            for (int i = 0; i < 4; i++)
                #pragma unroll
                for (int j = 0; j < 4; j++) acc[i][j] += a[i] * b[j];
        }
        __syncthreads();
    }
    #pragma unroll
    for (int i = 0; i < 4; i++) {
        int r = row0 + ty + 16*i;
        if (r >= NN) continue;
        #pragma unroll
        for (int j = 0; j < 4; j++) {
            int c = col0 + tx + 16*j;
            C[(size_t)r * 512 + c] = fmaxf(acc[i][j] + bc1[c], 0.f);
        }
    }
}

// ---------------- GAT attention dots ----------------
__global__ void att_dots_h8(const float* __restrict__ xl,
                            const float* __restrict__ asrc,
                            const float* __restrict__ adst)
{
    int w = (blockIdx.x * blockDim.x + threadIdx.x) >> 5;
    int lane = threadIdx.x & 31;
    if (w >= NN * HH) return;
    int n = w >> 3, h = w & 7;
    const float* xp = xl + (size_t)n * 512 + h * 64;
    const float* as = asrc + h * 64;
    const float* ad = adst + h * 64;
    float s = 0.f, d = 0.f;
    #pragma unroll
    for (int c = lane; c < 64; c += 32) { float v = xp[c]; s += v * as[c]; d += v * ad[c]; }
    #pragma unroll
    for (int o = 16; o; o >>= 1) { s += __shfl_down_sync(~0u, s, o); d += __shfl_down_sync(~0u, d, o); }
    if (!lane) { g_s1[w] = s; g_d1[w] = d; }
}

__global__ void att_dots_h1(const float* __restrict__ xl,
                            const float* __restrict__ asrc,
                            const float* __restrict__ adst)
{
    int n = (blockIdx.x * blockDim.x + threadIdx.x) >> 5;
    int lane = threadIdx.x & 31;
    if (n >= NN) return;
    const float* xp = xl + (size_t)n * 512;
    float s = 0.f, d = 0.f;
    #pragma unroll
    for (int c = lane; c < 512; c += 32) { float v = xp[c]; s += v * asrc[c]; d += v * adst[c]; }
    #pragma unroll
    for (int o = 16; o; o >>= 1) { s += __shfl_down_sync(~0u, s, o); d += __shfl_down_sync(~0u, d, o); }
    if (!lane) { g_s2[n] = s; g_d2[n] = d; }
}

// ---------------- segment softmax ----------------
__global__ void alpha_p1(const float* __restrict__ sarr, const float* __restrict__ darr,
                         const int* __restrict__ ei, float* __restrict__ alpha,
                         unsigned* __restrict__ amax, int Hh)
{
    int e = blockIdx.x * blockDim.x + threadIdx.x;
    if (e >= EEE) return;
    int s, d; edsd(ei, e, s, d);
    for (int h = 0; h < Hh; h++) {
        float a = sarr[s * Hh + h] + darr[d * Hh + h];
        a = (a > 0.f) ? a : 0.2f * a;
        alpha[(size_t)e * Hh + h] = a;
        atomicMax(&amax[d * Hh + h], enc_f(a));
    }
}

__global__ void alpha_p2(const int* __restrict__ ei, float* __restrict__ alpha,
                         const unsigned* __restrict__ amax, float* __restrict__ den, int Hh)
{
    int e = blockIdx.x * blockDim.x + threadIdx.x;
    if (e >= EEE) return;
    int s, d; edsd(ei, e, s, d);
    for (int h = 0; h < Hh; h++) {
        float m = dec_f(amax[d * Hh + h]);
        float ex = expf(alpha[(size_t)e * Hh + h] - m);
        alpha[(size_t)e * Hh + h] = ex;
        atomicAdd(&den[d * Hh + h], ex);
    }
}

__global__ void gat_aggregate(const float* __restrict__ alpha, const float* __restrict__ den,
                              const float* __restrict__ xl, float* __restrict__ out,
                              const int* __restrict__ ei, int Hh)
{
    int t = blockIdx.x * blockDim.x + threadIdx.x;
    if (t >= EEE * 128) return;
    int e = t >> 7, q = t & 127;
    int s, d; edsd(ei, e, s, d);
    int h = (Hh == 8) ? (q >> 4) : 0;
    float ex = alpha[(size_t)e * Hh + h];
    float w  = ex / (den[d * Hh + h] + 1e-16f);
    int c = q * 4;
    float4 v = *(const float4*)(xl + (size_t)s * 512 + c);
    float* o = out + (size_t)d * 512 + c;
    atomicAdd(o + 0, v.x * w);
    atomicAdd(o + 1, v.y * w);
    atomicAdd(o + 2, v.z * w);
    atomicAdd(o + 3, v.w * w);
}

__global__ void elu_bias(float* __restrict__ x, const float* __restrict__ b) {
    int i = blockIdx.x * blockDim.x + threadIdx.x;
    if (i >= NN * 512) return;
    float v = x[i] + b[i & 511];
    x[i] = (v > 0.f) ? v : expm1f(v);
}

// ---------------- synapse point branch ----------------
__global__ void point_max(const float* __restrict__ syn) {
    int e = blockIdx.x * blockDim.x + threadIdx.x;
    if (e >= EE) return;
    const float* p = syn + (size_t)e * PTSN * 6;
    #pragma unroll
    for (int j = 0; j < 6; j++) {
        float m = p[j];
        m = fmaxf(m, p[6  + j]);
        m = fmaxf(m, p[12 + j]);
        m = fmaxf(m, p[18 + j]);
        g_xp6[(size_t)e * 6 + j] = m;
    }
}

__global__ void count_deg(const int* __restrict__ ei) {
    int e = blockIdx.x * blockDim.x + threadIdx.x;
    if (e >= EE) return;
    atomicAdd(&g_cntL[ei[e]], 1.f);
    atomicAdd(&g_cntR[ei[EE + e]], 1.f);
}

__global__ void inv_counts() {
    int n = blockIdx.x * blockDim.x + threadIdx.x;
    if (n >= NN) return;
    g_invL[n] = 1.f / fmaxf(g_cntL[n], 1.f);
    g_invR[n] = 1.f / fmaxf(g_cntR[n], 1.f);
}

// ---------------- driver ----------------
extern "C" void kernel_launch(void* const* d_in, const int* in_sizes, int n_in,
                              void* d_out, int out_size)
{
    const int*   ei       = (const int*)  d_in[0];
    const float* synapse  = (const float*)d_in[2];
    const float* x_param  = (const float*)d_in[5];
    const float* W1       = (const float*)d_in[6];
    const float* att_src1 = (const float*)d_in[7];
    const float* att_dst1 = (const float*)d_in[8];
    const float* b1       = (const float*)d_in[9];
    const float* W2       = (const float*)d_in[10];
    const float* att_src2 = (const float*)d_in[11];
    const float* att_dst2 = (const float*)d_in[12];
    const float* b2       = (const float*)d_in[13];
    const float* We1      = (const float*)d_in[14];
    const float* be1      = (const float*)d_in[15];
    const float* We2      = (const float*)d_in[16];
    const float* be2      = (const float*)d_in[17];
    const float* Wc1      = (const float*)d_in[18];
    const float* bc1      = (const float*)d_in[19];
    const float* Wc2      = (const float*)d_in[20];
    const float* bc2      = (const float*)d_in[21];
    float* out = (float*)d_out;

    float* p_poolA  = nullptr; cudaGetSymbolAddress((void**)&p_poolA,  g_poolA);
    float* p_out1   = nullptr; cudaGetSymbolAddress((void**)&p_out1,   g_out1);
    float* p_xl2    = nullptr; cudaGetSymbolAddress((void**)&p_xl2,    g_xl2);
    float* p_out2   = nullptr; cudaGetSymbolAddress((void**)&p_out2,   g_out2);
    float* p_a1     = nullptr; cudaGetSymbolAddress((void**)&p_a1,     g_alpha1);
    float* p_a2     = nullptr; cudaGetSymbolAddress((void**)&p_a2,     g_alpha2);
    unsigned* p_am1 = nullptr; cudaGetSymbolAddress((void**)&p_am1,    g_amax1);
    unsigned* p_am2 = nullptr; cudaGetSymbolAddress((void**)&p_am2,    g_amax2);
    float* p_den1   = nullptr; cudaGetSymbolAddress((void**)&p_den1,   g_den1);
    float* p_den2   = nullptr; cudaGetSymbolAddress((void**)&p_den2,   g_den2);
    float* p_s1     = nullptr; cudaGetSymbolAddress((void**)&p_s1,     g_s1);
    float* p_d1     = nullptr; cudaGetSymbolAddress((void**)&p_d1,     g_d1);
    float* p_s2     = nullptr; cudaGetSymbolAddress((void**)&p_s2,     g_s2);
    float* p_d2     = nullptr; cudaGetSymbolAddress((void**)&p_d2,     g_d2);

    float* p_xl1    = p_poolA;   // live only during GAT layer 1
    float* p_finalh = p_poolA;   // reused for classifier hidden (xl1 dead)

    zero_kernel<<<(NN*512 + 255) / 256, 256>>>();

    // ---- GAT layer 1 ----
    gemm64<0><<<dim3(512/64, (NN + 63)/64), 256>>>(x_param, W1, nullptr, p_xl1, NN, 512, FF);
    att_dots_h8<<<(NN*HH*32 + 255)/256, 256>>>(p_xl1, att_src1, att_dst1);
    alpha_p1<<<(EEE + 255)/256, 256>>>(p_s1, p_d1, ei, p_a1, p_am1, HH);
    alpha_p2<<<(EEE + 255)/256, 256>>>(ei, p_a1, p_am1, p_den1, HH);
    gat_aggregate<<<(EEE*128 + 255)/256, 256>>>(p_a1, p_den1, p_xl1, p_out1, ei, HH);
    elu_bias<<<(NN*512 + 255)/256, 256>>>(p_out1, b1);

    // ---- GAT layer 2 ----
    gemm64<0><<<dim3(512/64, (NN + 63)/64), 256>>>(p_out1, W2, nullptr, p_xl2, NN, 512, 512);
    att_dots_h1<<<(NN*32 + 255)/256, 256>>>(p_xl2, att_src2, att_dst2);
    alpha_p1<<<(EEE + 255)/256, 256>>>(p_s2, p_d2, ei, p_a2, p_am2, 1);
    alpha_p2<<<(EEE + 255)/256, 256>>>(ei, p_a2, p_am2, p_den2, 1);
    gat_aggregate<<<(EEE*128 + 255)/256, 256>>>(p_a2, p_den2, p_xl2, p_out2, ei, 1);

    // ---- synapse point branch ----
    point_max<<<(EE + 255)/256, 256>>>(synapse);
    count_deg<<<(EE + 255)/256, 256>>>(ei);
    inv_counts<<<(NN + 255)/256, 256>>>();
    edge_gemm_scatter<<<dim3(512/64, EE/64), 256>>>(We1, be1, We2, be2, ei);

    // ---- classifier ----
    gemm64_final<<<dim3(512/64, (NN + 63)/64), 256>>>(b2, Wc1, bc1, p_finalh);
    gemm64<0><<<dim3((NCLSC + 63)/64, (NN + 63)/64), 256>>>(p_finalh, Wc2, bc2, out, NN, NCLSC, 512);
}

// round 5
// speedup vs baseline: 1.3631x; 1.3631x over previous
#include <cuda_runtime.h>
#include <cuda_bf16.h>
#include <mma.h>
#include <math.h>

using namespace nvcuda;

// ---------------- problem constants ----------------
#define NN   20000
#define NNP  20096          // 157*128, padded node count for guard-free wmma tiles
#define FF   128
#define HH   8
#define EE   200000
#define PTSN 4
#define EEE  (EE+NN)
#define NCLSC 133

// ---------------- scratch (device globals; zero-initialized at load) -------
__device__ float    g_poolA[(size_t)NNP*512];   // xl1 (layer1) then finalh
__device__ float    g_s1[NN*HH];
__device__ float    g_d1[NN*HH];
__device__ unsigned g_amax1[NN*HH];
__device__ float    g_den1[NN*HH];
__device__ float    g_alpha1[(size_t)EEE*HH];
__device__ float    g_out1[(size_t)NNP*512];
__device__ float    g_xl2[(size_t)NNP*512];
__device__ float    g_s2[NN];
__device__ float    g_d2[NN];
__device__ unsigned g_amax2[NN];
__device__ float    g_den2[NN];
__device__ float    g_alpha2[EEE];
__device__ float    g_out2[(size_t)NNP*512];
__device__ float    g_xp6[EE*6];
__device__ float    g_leftsum[(size_t)NNP*512];
__device__ float    g_rightsum[(size_t)NNP*512];
__device__ float    g_invL[NNP];
__device__ float    g_invR[NNP];
__device__ float    g_cntL[NN];
__device__ float    g_cntR[NN];

// ---------------- helpers ----------------
__device__ __forceinline__ unsigned enc_f(float f) {
    unsigned u = __float_as_uint(f);
    return (u & 0x80000000u) ? ~u : (u | 0x80000000u);
}
__device__ __forceinline__ float dec_f(unsigned u) {
    return (u & 0x80000000u) ? __uint_as_float(u & 0x7FFFFFFFu)
                             : __uint_as_float(~u);
}
__device__ __forceinline__ void edsd(const int* __restrict__ ei, int e, int& s, int& d) {
    if (e < EE) { s = ei[e]; d = ei[EE + e]; }
    else        { s = d = e - EE; }
}

// ---------------- zero/init ----------------
__global__ void zero_kernel() {
    int i = blockIdx.x * blockDim.x + threadIdx.x;
    if (i < NN*512) {
        g_out1[i] = 0.f; g_out2[i] = 0.f;
        g_leftsum[i] = 0.f; g_rightsum[i] = 0.f;
    }
    if (i < NN*HH) { g_amax1[i] = 0u; g_den1[i] = 0.f; }
    if (i < NN)    { g_amax2[i] = 0u; g_den2[i] = 0.f; g_cntL[i] = 0.f; g_cntR[i] = 0.f; }
}

// ================= tf32 wmma GEMM framework =================
// block tile 128x64, K-chunk 32, 8 warps (warp tile 32x32), m16n16k8 tf32
#define BKP 40   // As leading dim (mult of 4 elems = 16B)
#define BNP 72   // Bs / Cs leading dim

typedef wmma::fragment<wmma::matrix_a, 16, 16, 8, wmma::precision::tf32, wmma::row_major> FragA;
typedef wmma::fragment<wmma::matrix_b, 16, 16, 8, wmma::precision::tf32, wmma::row_major> FragB;
typedef wmma::fragment<wmma::accumulator, 16, 16, 8, float> FragC;

__device__ __forceinline__ void wmma_chunk(
    const float (*As)[BKP], const float (*Bs)[BNP],
    int warp_m, int warp_n, FragC acc[2][2])
{
    #pragma unroll
    for (int ks = 0; ks < 4; ks++) {
        FragA a[2]; FragB b[2];
        #pragma unroll
        for (int i = 0; i < 2; i++) {
            wmma::load_matrix_sync(a[i], &As[warp_m*32 + i*16][ks*8], BKP);
            #pragma unroll
            for (int t = 0; t < a[i].num_elements; t++)
                a[i].x[t] = wmma::__float_to_tf32(a[i].x[t]);
        }
        #pragma unroll
        for (int j = 0; j < 2; j++) {
            wmma::load_matrix_sync(b[j], &Bs[ks*8][warp_n*32 + j*16], BNP);
            #pragma unroll
            for (int t = 0; t < b[j].num_elements; t++)
                b[j].x[t] = wmma::__float_to_tf32(b[j].x[t]);
        }
        #pragma unroll
        for (int i = 0; i < 2; i++)
            #pragma unroll
            for (int j = 0; j < 2; j++)
                wmma::mma_sync(acc[i][j], a[i], b[j], acc[i][j]);
    }
}

// ---- plain wmma GEMM, direct store (rows padded; no guards). C[M,Nc] = A@B
__global__ __launch_bounds__(256)
void wmma_gemm_direct(const float* __restrict__ A, const float* __restrict__ B,
                      float* __restrict__ C, int Nc, int K)
{
    __shared__ float As[128][BKP];
    __shared__ float Bs[32][BNP];
    int tid = threadIdx.x;
    int wid = tid >> 5;
    int warp_m = wid & 3, warp_n = wid >> 2;
    int row0 = blockIdx.y * 128, col0 = blockIdx.x * 64;
    FragC acc[2][2];
    #pragma unroll
    for (int i = 0; i < 2; i++)
        #pragma unroll
        for (int j = 0; j < 2; j++) wmma::fill_fragment(acc[i][j], 0.f);

    for (int k0 = 0; k0 < K; k0 += 32) {
        #pragma unroll
        for (int i = 0; i < 4; i++) {
            int idx = tid + i * 256;               // 1024 float4
            int r = idx >> 3, c4 = idx & 7;
            *(float4*)&As[r][c4*4] = *(const float4*)&A[(size_t)(row0 + r) * K + k0 + c4*4];
        }
        #pragma unroll
        for (int i = 0; i < 2; i++) {
            int idx = tid + i * 256;               // 512 float4
            int r = idx >> 4, c4 = idx & 15;
            *(float4*)&Bs[r][c4*4] = *(const float4*)&B[(size_t)(k0 + r) * Nc + col0 + c4*4];
        }
        __syncthreads();
        wmma_chunk(As, Bs, warp_m, warp_n, acc);
        __syncthreads();
    }
    #pragma unroll
    for (int i = 0; i < 2; i++)
        #pragma unroll
        for (int j = 0; j < 2; j++)
            wmma::store_matrix_sync(
                &C[(size_t)(row0 + warp_m*32 + i*16) * Nc + col0 + warp_n*32 + j*16],
                acc[i][j], Nc, wmma::mem_row_major);
}

// ---- fused edge branch: A = relu(xp6 @ We1 + be1) built in smem per chunk;
//      (A @ We2 + be2) scattered into leftsum[src]/rightsum[dst]
__global__ __launch_bounds__(256)
void wmma_edge_scatter(const float* __restrict__ We1, const float* __restrict__ be1,
                       const float* __restrict__ We2, const float* __restrict__ be2,
                       const int* __restrict__ ei)
{
    __shared__ union {
        struct { float As[128][BKP]; float Bs[32][BNP]; } s;
        float Cs[128][BNP];
    } u;
    __shared__ float Xs[128][6];
    int tid = threadIdx.x;
    int wid = tid >> 5;
    int warp_m = wid & 3, warp_n = wid >> 2;
    int row0 = blockIdx.y * 128, col0 = blockIdx.x * 64;

    for (int idx = tid; idx < 128 * 6; idx += 256) {
        int m = idx / 6, j = idx % 6;
        int gr = row0 + m;
        Xs[m][j] = (gr < EE) ? g_xp6[(size_t)gr * 6 + j] : 0.f;
    }
    __syncthreads();

    FragC acc[2][2];
    #pragma unroll
    for (int i = 0; i < 2; i++)
        #pragma unroll
        for (int j = 0; j < 2; j++) wmma::fill_fragment(acc[i][j], 0.f);

    for (int k0 = 0; k0 < 256; k0 += 32) {
        #pragma unroll
        for (int i = 0; i < 16; i++) {             // 4096 scalar elems
            int idx = tid + i * 256;
            int m = idx >> 5, kk = idx & 31;
            int gk = k0 + kk;
            float v = be1[gk];
            #pragma unroll
            for (int j = 0; j < 6; j++) v += Xs[m][j] * We1[j * 256 + gk];
            u.s.As[m][kk] = fmaxf(v, 0.f);
        }
        #pragma unroll
        for (int i = 0; i < 2; i++) {
            int idx = tid + i * 256;
            int r = idx >> 4, c4 = idx & 15;
            *(float4*)&u.s.Bs[r][c4*4] = *(const float4*)&We2[(size_t)(k0 + r) * 512 + col0 + c4*4];
        }
        __syncthreads();
        wmma_chunk(u.s.As, u.s.Bs, warp_m, warp_n, acc);
        __syncthreads();
    }

    // stage C tile to smem, then scatter with atomics
    #pragma unroll
    for (int i = 0; i < 2; i++)
        #pragma unroll
        for (int j = 0; j < 2; j++)
            wmma::store_matrix_sync(&u.Cs[warp_m*32 + i*16][warp_n*32 + j*16],
                                    acc[i][j], BNP, wmma::mem_row_major);
    __syncthreads();

    int r = tid >> 1, half = tid & 1;
    int gr = row0 + r;
    if (gr < EE) {
        int s = ei[gr], d = ei[EE + gr];
        float* Lp = &g_leftsum [(size_t)s * 512 + col0];
        float* Rp = &g_rightsum[(size_t)d * 512 + col0];
        #pragma unroll
        for (int c = 0; c < 32; c++) {
            int col = half * 32 + c;
            float v = u.Cs[r][col] + be2[col0 + col];
            atomicAdd(Lp + col, v);
            atomicAdd(Rp + col, v);
        }
    }
}

// ---- classifier GEMM; A = [out2+b2 | left*invL | right*invR] (virtual concat)
__global__ __launch_bounds__(256)
void wmma_classifier(const float* __restrict__ b2, const float* __restrict__ Wc1,
                     const float* __restrict__ bc1, float* __restrict__ C)
{
    __shared__ union {
        struct { float As[128][BKP]; float Bs[32][BNP]; } s;
        float Cs[128][BNP];
    } u;
    int tid = threadIdx.x;
    int wid = tid >> 5;
    int warp_m = wid & 3, warp_n = wid >> 2;
    int row0 = blockIdx.y * 128, col0 = blockIdx.x * 64;

    FragC acc[2][2];
    #pragma unroll
    for (int i = 0; i < 2; i++)
        #pragma unroll
        for (int j = 0; j < 2; j++) wmma::fill_fragment(acc[i][j], 0.f);

    for (int k0 = 0; k0 < 1536; k0 += 32) {
        int seg = k0 >> 9;                 // 0: out2+b2, 1: left*invL, 2: right*invR
        int kb  = k0 & 511;
        #pragma unroll
        for (int i = 0; i < 4; i++) {
            int idx = tid + i * 256;
            int r = idx >> 3, c4 = idx & 7;
            int gr = row0 + r, gk = kb + c4*4;
            float4 v;
            if (seg == 0) {
                v = *(const float4*)&g_out2[(size_t)gr * 512 + gk];
                float4 bb = *(const float4*)&b2[gk];
                v.x += bb.x; v.y += bb.y; v.z += bb.z; v.w += bb.w;
            } else if (seg == 1) {
                v = *(const float4*)&g_leftsum[(size_t)gr * 512 + gk];
                float s = g_invL[gr];
                v.x *= s; v.y *= s; v.z *= s; v.w *= s;
            } else {
                v = *(const float4*)&g_rightsum[(size_t)gr * 512 + gk];
                float s = g_invR[gr];
                v.x *= s; v.y *= s; v.z *= s; v.w *= s;
            }
            *(float4*)&u.s.As[r][c4*4] = v;
        }
        #pragma unroll
        for (int i = 0; i < 2; i++) {
            int idx = tid + i * 256;
            int r = idx >> 4, c4 = idx & 15;
            *(float4*)&u.s.Bs[r][c4*4] = *(const float4*)&Wc1[(size_t)(k0 + r) * 512 + col0 + c4*4];
        }
        __syncthreads();
        wmma_chunk(u.s.As, u.s.Bs, warp_m, warp_n, acc);
        __syncthreads();
    }

    #pragma unroll
    for (int i = 0; i < 2; i++)
        #pragma unroll
        for (int j = 0; j < 2; j++)
            wmma::store_matrix_sync(&u.Cs[warp_m*32 + i*16][warp_n*32 + j*16],
                                    acc[i][j], BNP, wmma::mem_row_major);
    __syncthreads();

    int r = tid >> 1, half = tid & 1;
    int gr = row0 + r;
    #pragma unroll
    for (int c = 0; c < 32; c++) {
        int col = half * 32 + c;
        C[(size_t)gr * 512 + col0 + col] = fmaxf(u.Cs[r][col] + bc1[col0 + col], 0.f);
    }
}

// ---------------- fp32 fallback GEMM (small shapes) ----------------
template<int ACT>
__global__ __launch_bounds__(256)
void gemm64(const float* __restrict__ A, const float* __restrict__ B,
            const float* __restrict__ bias, float* __restrict__ C,
            int M, int Nc, int K)
{
    __shared__ float As[16][65];
    __shared__ float Bs[16][65];
    int tid = threadIdx.x;
    int tx = tid & 15, ty = tid >> 4;
    int row0 = blockIdx.y * 64, col0 = blockIdx.x * 64;
    float acc[4][4] = {};
    for (int k0 = 0; k0 < K; k0 += 16) {
        #pragma unroll
        for (int i = 0; i < 4; i++) {
            int idx = tid + i * 256;
            int m = idx >> 4, kk = idx & 15;
            int gr = row0 + m;
            As[kk][m] = (gr < M) ? A[(size_t)gr * K + k0 + kk] : 0.f;
        }
        #pragma unroll
        for (int i = 0; i < 4; i++) {
            int idx = tid + i * 256;
            int kk = idx >> 6, n = idx & 63;
            int gc = col0 + n;
            Bs[kk][n] = (gc < Nc) ? B[(size_t)(k0 + kk) * Nc + gc] : 0.f;
        }
        __syncthreads();
        #pragma unroll
        for (int kk = 0; kk < 16; kk++) {
            float a[4], b[4];
            #pragma unroll
            for (int i = 0; i < 4; i++) a[i] = As[kk][ty + 16*i];
            #pragma unroll
            for (int j = 0; j < 4; j++) b[j] = Bs[kk][tx + 16*j];
            #pragma unroll
            for (int i = 0; i < 4; i++)
                #pragma unroll
                for (int j = 0; j < 4; j++) acc[i][j] += a[i] * b[j];
        }
        __syncthreads();
    }
    #pragma unroll
    for (int i = 0; i < 4; i++) {
        int r = row0 + ty + 16*i;
        if (r >= M) continue;
        #pragma unroll
        for (int j = 0; j < 4; j++) {
            int c = col0 + tx + 16*j;
            if (c >= Nc) continue;
            float v = acc[i][j];
            if (bias) v += bias[c];
            if (ACT == 1) v = fmaxf(v, 0.f);
            C[(size_t)r * Nc + c] = v;
        }
    }
}

// ---------------- GAT attention dots ----------------
__global__ void att_dots_h8(const float* __restrict__ xl,
                            const float* __restrict__ asrc,
                            const float* __restrict__ adst)
{
    int w = (blockIdx.x * blockDim.x + threadIdx.x) >> 5;
    int lane = threadIdx.x & 31;
    if (w >= NN * HH) return;
    int n = w >> 3, h = w & 7;
    const float* xp = xl + (size_t)n * 512 + h * 64;
    const float* as = asrc + h * 64;
    const float* ad = adst + h * 64;
    float s = 0.f, d = 0.f;
    #pragma unroll
    for (int c = lane; c < 64; c += 32) { float v = xp[c]; s += v * as[c]; d += v * ad[c]; }
    #pragma unroll
    for (int o = 16; o; o >>= 1) { s += __shfl_down_sync(~0u, s, o); d += __shfl_down_sync(~0u, d, o); }
    if (!lane) { g_s1[w] = s; g_d1[w] = d; }
}

__global__ void att_dots_h1(const float* __restrict__ xl,
                            const float* __restrict__ asrc,
                            const float* __restrict__ adst)
{
    int n = (blockIdx.x * blockDim.x + threadIdx.x) >> 5;
    int lane = threadIdx.x & 31;
    if (n >= NN) return;
    const float* xp = xl + (size_t)n * 512;
    float s = 0.f, d = 0.f;
    #pragma unroll
    for (int c = lane; c < 512; c += 32) { float v = xp[c]; s += v * asrc[c]; d += v * adst[c]; }
    #pragma unroll
    for (int o = 16; o; o >>= 1) { s += __shfl_down_sync(~0u, s, o); d += __shfl_down_sync(~0u, d, o); }
    if (!lane) { g_s2[n] = s; g_d2[n] = d; }
}

// ---------------- segment softmax ----------------
__global__ void alpha_p1(const float* __restrict__ sarr, const float* __restrict__ darr,
                         const int* __restrict__ ei, float* __restrict__ alpha,
                         unsigned* __restrict__ amax, int Hh)
{
    int e = blockIdx.x * blockDim.x + threadIdx.x;
    if (e >= EEE) return;
    int s, d; edsd(ei, e, s, d);
    for (int h = 0; h < Hh; h++) {
        float a = sarr[s * Hh + h] + darr[d * Hh + h];
        a = (a > 0.f) ? a : 0.2f * a;
        alpha[(size_t)e * Hh + h] = a;
        atomicMax(&amax[d * Hh + h], enc_f(a));
    }
}

__global__ void alpha_p2(const int* __restrict__ ei, float* __restrict__ alpha,
                         const unsigned* __restrict__ amax, float* __restrict__ den, int Hh)
{
    int e = blockIdx.x * blockDim.x + threadIdx.x;
    if (e >= EEE) return;
    int s, d; edsd(ei, e, s, d);
    for (int h = 0; h < Hh; h++) {
        float m = dec_f(amax[d * Hh + h]);
        float ex = expf(alpha[(size_t)e * Hh + h] - m);
        alpha[(size_t)e * Hh + h] = ex;
        atomicAdd(&den[d * Hh + h], ex);
    }
}

__global__ void gat_aggregate(const float* __restrict__ alpha, const float* __restrict__ den,
                              const float* __restrict__ xl, float* __restrict__ out,
                              const int* __restrict__ ei, int Hh)
{
    int t = blockIdx.x * blockDim.x + threadIdx.x;
    if (t >= EEE * 128) return;
    int e = t >> 7, q = t & 127;
    int s, d; edsd(ei, e, s, d);
    int h = (Hh == 8) ? (q >> 4) : 0;
    float ex = alpha[(size_t)e * Hh + h];
    float w  = ex / (den[d * Hh + h] + 1e-16f);
    int c = q * 4;
    float4 v = *(const float4*)(xl + (size_t)s * 512 + c);
    float* o = out + (size_t)d * 512 + c;
    atomicAdd(o + 0, v.x * w);
    atomicAdd(o + 1, v.y * w);
    atomicAdd(o + 2, v.z * w);
    atomicAdd(o + 3, v.w * w);
}

__global__ void elu_bias(float* __restrict__ x, const float* __restrict__ b) {
    int i = blockIdx.x * blockDim.x + threadIdx.x;
    if (i >= NN * 512) return;
    float v = x[i] + b[i & 511];
    x[i] = (v > 0.f) ? v : expm1f(v);
}

// ---------------- synapse point branch ----------------
__global__ void point_max(const float* __restrict__ syn) {
    int e = blockIdx.x * blockDim.x + threadIdx.x;
    if (e >= EE) return;
    const float* p = syn + (size_t)e * PTSN * 6;
    #pragma unroll
    for (int j = 0; j < 6; j++) {
        float m = p[j];
        m = fmaxf(m, p[6  + j]);
        m = fmaxf(m, p[12 + j]);
        m = fmaxf(m, p[18 + j]);
        g_xp6[(size_t)e * 6 + j] = m;
    }
}

__global__ void count_deg(const int* __restrict__ ei) {
    int e = blockIdx.x * blockDim.x + threadIdx.x;
    if (e >= EE) return;
    atomicAdd(&g_cntL[ei[e]], 1.f);
    atomicAdd(&g_cntR[ei[EE + e]], 1.f);
}

__global__ void inv_counts() {
    int n = blockIdx.x * blockDim.x + threadIdx.x;
    if (n >= NN) return;
    g_invL[n] = 1.f / fmaxf(g_cntL[n], 1.f);
    g_invR[n] = 1.f / fmaxf(g_cntR[n], 1.f);
}

// ---------------- driver ----------------
extern "C" void kernel_launch(void* const* d_in, const int* in_sizes, int n_in,
                              void* d_out, int out_size)
{
    const int*   ei       = (const int*)  d_in[0];
    const float* synapse  = (const float*)d_in[2];
    const float* x_param  = (const float*)d_in[5];
    const float* W1       = (const float*)d_in[6];
    const float* att_src1 = (const float*)d_in[7];
    const float* att_dst1 = (const float*)d_in[8];
    const float* b1       = (const float*)d_in[9];
    const float* W2       = (const float*)d_in[10];
    const float* att_src2 = (const float*)d_in[11];
    const float* att_dst2 = (const float*)d_in[12];
    const float* b2       = (const float*)d_in[13];
    const float* We1      = (const float*)d_in[14];
    const float* be1      = (const float*)d_in[15];
    const float* We2      = (const float*)d_in[16];
    const float* be2      = (const float*)d_in[17];
    const float* Wc1      = (const float*)d_in[18];
    const float* bc1      = (const float*)d_in[19];
    const float* Wc2      = (const float*)d_in[20];
    const float* bc2      = (const float*)d_in[21];
    float* out = (float*)d_out;

    float* p_poolA  = nullptr; cudaGetSymbolAddress((void**)&p_poolA,  g_poolA);
    float* p_out1   = nullptr; cudaGetSymbolAddress((void**)&p_out1,   g_out1);
    float* p_xl2    = nullptr; cudaGetSymbolAddress((void**)&p_xl2,    g_xl2);
    float* p_out2   = nullptr; cudaGetSymbolAddress((void**)&p_out2,   g_out2);
    float* p_a1     = nullptr; cudaGetSymbolAddress((void**)&p_a1,     g_alpha1);
    float* p_a2     = nullptr; cudaGetSymbolAddress((void**)&p_a2,     g_alpha2);
    unsigned* p_am1 = nullptr; cudaGetSymbolAddress((void**)&p_am1,    g_amax1);
    unsigned* p_am2 = nullptr; cudaGetSymbolAddress((void**)&p_am2,    g_amax2);
    float* p_den1   = nullptr; cudaGetSymbolAddress((void**)&p_den1,   g_den1);
    float* p_den2   = nullptr; cudaGetSymbolAddress((void**)&p_den2,   g_den2);
    float* p_s1     = nullptr; cudaGetSymbolAddress((void**)&p_s1,     g_s1);
    float* p_d1     = nullptr; cudaGetSymbolAddress((void**)&p_d1,     g_d1);
    float* p_s2     = nullptr; cudaGetSymbolAddress((void**)&p_s2,     g_s2);
    float* p_d2     = nullptr; cudaGetSymbolAddress((void**)&p_d2,     g_d2);

    float* p_xl1    = p_poolA;   // live only during GAT layer 1
    float* p_finalh = p_poolA;   // reused for classifier hidden (xl1 dead)

    zero_kernel<<<(NN*512 + 255) / 256, 256>>>();

    // ---- GAT layer 1 (fp32 gemm: K=128, small) ----
    gemm64<0><<<dim3(512/64, (NN + 63)/64), 256>>>(x_param, W1, nullptr, p_xl1, NN, 512, FF);
    att_dots_h8<<<(NN*HH*32 + 255)/256, 256>>>(p_xl1, att_src1, att_dst1);
    alpha_p1<<<(EEE + 255)/256, 256>>>(p_s1, p_d1, ei, p_a1, p_am1, HH);
    alpha_p2<<<(EEE + 255)/256, 256>>>(ei, p_a1, p_am1, p_den1, HH);
    gat_aggregate<<<(EEE*128 + 255)/256, 256>>>(p_a1, p_den1, p_xl1, p_out1, ei, HH);
    elu_bias<<<(NN*512 + 255)/256, 256>>>(p_out1, b1);

    // ---- GAT layer 2 (tf32 wmma) ----
    wmma_gemm_direct<<<dim3(512/64, NNP/128), 256>>>(p_out1, W2, p_xl2, 512, 512);
    att_dots_h1<<<(NN*32 + 255)/256, 256>>>(p_xl2, att_src2, att_dst2);
    alpha_p1<<<(EEE + 255)/256, 256>>>(p_s2, p_d2, ei, p_a2, p_am2, 1);
    alpha_p2<<<(EEE + 255)/256, 256>>>(ei, p_a2, p_am2, p_den2, 1);
    gat_aggregate<<<(EEE*128 + 255)/256, 256>>>(p_a2, p_den2, p_xl2, p_out2, ei, 1);

    // ---- synapse point branch (tf32 wmma + fused scatter) ----
    point_max<<<(EE + 255)/256, 256>>>(synapse);
    count_deg<<<(EE + 255)/256, 256>>>(ei);
    inv_counts<<<(NN + 255)/256, 256>>>();
    wmma_edge_scatter<<<dim3(512/64, (EE + 127)/128), 256>>>(We1, be1, We2, be2, ei);

    // ---- classifier (tf32 wmma, virtual concat A) ----
    wmma_classifier<<<dim3(512/64, NNP/128), 256>>>(b2, Wc1, bc1, p_finalh);
    gemm64<0><<<dim3((NCLSC + 63)/64, (NN + 63)/64), 256>>>(p_finalh, Wc2, bc2, out, NN, NCLSC, 512);
}

// round 7
// speedup vs baseline: 1.8878x; 1.3849x over previous
#include <cuda_runtime.h>
#include <cuda_bf16.h>
#include <mma.h>
#include <math.h>

using namespace nvcuda;

// ---------------- problem constants ----------------
#define NN   20000
#define NNP  20096          // 157*128, padded node count for guard-free wmma tiles
#define FF   128
#define HH   8
#define EE   200000
#define PTSN 4
#define EEE  (EE+NN)
#define NCLSC 133

// ---------------- scratch (device globals; zero-initialized at load) -------
__device__ float    g_poolA[(size_t)NNP*512];   // xl1 (layer1) then finalh
__device__ float    g_s1[NN*HH];
__device__ float    g_d1[NN*HH];
__device__ unsigned g_amax1[NN*HH];
__device__ float    g_den1[NN*HH];
__device__ float    g_alpha1[(size_t)EEE*HH];
__device__ float    g_out1[(size_t)NNP*512];
__device__ float    g_xl2[(size_t)NNP*512];
__device__ float    g_s2[NN];
__device__ float    g_d2[NN];
__device__ unsigned g_amax2[NN];
__device__ float    g_den2[NN];
__device__ float    g_alpha2[EEE];
__device__ float    g_out2[(size_t)NNP*512];
__device__ float    g_xp6[EE*6];
__device__ float    g_leftsum[(size_t)NNP*512];
__device__ float    g_rightsum[(size_t)NNP*512];
__device__ float    g_invL[NNP];
__device__ float    g_invR[NNP];
__device__ float    g_cntL[NN];
__device__ float    g_cntR[NN];

// ---------------- helpers ----------------
__device__ __forceinline__ unsigned enc_f(float f) {
    unsigned u = __float_as_uint(f);
    return (u & 0x80000000u) ? ~u : (u | 0x80000000u);
}
__device__ __forceinline__ float dec_f(unsigned u) {
    return (u & 0x80000000u) ? __uint_as_float(u & 0x7FFFFFFFu)
                             : __uint_as_float(~u);
}
__device__ __forceinline__ void edsd(const int* __restrict__ ei, int e, int& s, int& d) {
    if (e < EE) { s = ei[e]; d = ei[EE + e]; }
    else        { s = d = e - EE; }
}
// vectorized global reduction (sm_90+): 4 adds in one instruction
__device__ __forceinline__ void red_add_v4(float* p, float4 v) {
    asm volatile("red.global.add.v4.f32 [%0], {%1,%2,%3,%4};"
                 :: "l"(p), "f"(v.x), "f"(v.y), "f"(v.z), "f"(v.w) : "memory");
}

// ---------------- zero/init ----------------
__global__ void zero_kernel() {
    int i = blockIdx.x * blockDim.x + threadIdx.x;
    if (i < NN*512) {
        g_out1[i] = 0.f; g_out2[i] = 0.f;
        g_leftsum[i] = 0.f; g_rightsum[i] = 0.f;
    }
    if (i < NN*HH) { g_amax1[i] = 0u; g_den1[i] = 0.f; }
    if (i < NN)    { g_amax2[i] = 0u; g_den2[i] = 0.f; g_cntL[i] = 0.f; g_cntR[i] = 0.f; }
}

// ================= tf32 wmma GEMM framework =================
// block tile 128x64, K-chunk 32, 8 warps (warp tile 32x32), m16n16k8 tf32
// values are pre-rounded to tf32 at smem staging (no per-fragment cvt)
#define BKP 40   // As leading dim
#define BNP 72   // Bs / Cs leading dim

typedef wmma::fragment<wmma::matrix_a, 16, 16, 8, wmma::precision::tf32, wmma::row_major> FragA;
typedef wmma::fragment<wmma::matrix_b, 16, 16, 8, wmma::precision::tf32, wmma::row_major> FragB;
typedef wmma::fragment<wmma::accumulator, 16, 16, 8, float> FragC;

__device__ __forceinline__ float4 tf32_4(float4 v) {
    v.x = wmma::__float_to_tf32(v.x); v.y = wmma::__float_to_tf32(v.y);
    v.z = wmma::__float_to_tf32(v.z); v.w = wmma::__float_to_tf32(v.w);
    return v;
}

__device__ __forceinline__ void wmma_chunk(
    const float (*As)[BKP], const float (*Bs)[BNP],
    int warp_m, int warp_n, FragC acc[2][2])
{
    #pragma unroll
    for (int ks = 0; ks < 4; ks++) {
        FragA a[2]; FragB b[2];
        #pragma unroll
        for (int i = 0; i < 2; i++)
            wmma::load_matrix_sync(a[i], &As[warp_m*32 + i*16][ks*8], BKP);
        #pragma unroll
        for (int j = 0; j < 2; j++)
            wmma::load_matrix_sync(b[j], &Bs[ks*8][warp_n*32 + j*16], BNP);
        #pragma unroll
        for (int i = 0; i < 2; i++)
            #pragma unroll
            for (int j = 0; j < 2; j++)
                wmma::mma_sync(acc[i][j], a[i], b[j], acc[i][j]);
    }
}

// ---- plain wmma GEMM, direct store. GUARD: clamp A rows >= Mreal to zero.
template<bool GUARD>
__global__ __launch_bounds__(256)
void wmma_gemm_direct(const float* __restrict__ A, const float* __restrict__ B,
                      float* __restrict__ C, int Nc, int K, int Mreal)
{
    __shared__ float As[128][BKP];
    __shared__ float Bs[32][BNP];
    int tid = threadIdx.x;
    int wid = tid >> 5;
    int warp_m = wid & 3, warp_n = wid >> 2;
    int row0 = blockIdx.y * 128, col0 = blockIdx.x * 64;
    FragC acc[2][2];
    #pragma unroll
    for (int i = 0; i < 2; i++)
        #pragma unroll
        for (int j = 0; j < 2; j++) wmma::fill_fragment(acc[i][j], 0.f);

    for (int k0 = 0; k0 < K; k0 += 32) {
        #pragma unroll
        for (int i = 0; i < 4; i++) {
            int idx = tid + i * 256;               // 1024 float4
            int r = idx >> 3, c4 = idx & 7;
            float4 v = make_float4(0.f, 0.f, 0.f, 0.f);
            if (!GUARD || (row0 + r) < Mreal)
                v = *(const float4*)&A[(size_t)(row0 + r) * K + k0 + c4*4];
            *(float4*)&As[r][c4*4] = tf32_4(v);
        }
        #pragma unroll
        for (int i = 0; i < 2; i++) {
            int idx = tid + i * 256;               // 512 float4
            int r = idx >> 4, c4 = idx & 15;
            float4 v = *(const float4*)&B[(size_t)(k0 + r) * Nc + col0 + c4*4];
            *(float4*)&Bs[r][c4*4] = tf32_4(v);
        }
        __syncthreads();
        wmma_chunk(As, Bs, warp_m, warp_n, acc);
        __syncthreads();
    }
    #pragma unroll
    for (int i = 0; i < 2; i++)
        #pragma unroll
        for (int j = 0; j < 2; j++)
            wmma::store_matrix_sync(
                &C[(size_t)(row0 + warp_m*32 + i*16) * Nc + col0 + warp_n*32 + j*16],
                acc[i][j], Nc, wmma::mem_row_major);
}

// ---- fused edge branch: A = relu(xp6 @ We1 + be1) built in smem per chunk;
//      (A @ We2 + be2) scattered into leftsum[src]/rightsum[dst] via red.v4
__global__ __launch_bounds__(256)
void wmma_edge_scatter(const float* __restrict__ We1, const float* __restrict__ be1,
                       const float* __restrict__ We2, const float* __restrict__ be2,
                       const int* __restrict__ ei)
{
    __shared__ union {
        struct { float As[128][BKP]; float Bs[32][BNP]; } s;
        float Cs[128][BNP];
    } u;
    __shared__ float Xs[128][6];
    int tid = threadIdx.x;
    int wid = tid >> 5;
    int warp_m = wid & 3, warp_n = wid >> 2;
    int row0 = blockIdx.y * 128, col0 = blockIdx.x * 64;

    for (int idx = tid; idx < 128 * 6; idx += 256) {
        int m = idx / 6, j = idx % 6;
        int gr = row0 + m;
        Xs[m][j] = (gr < EE) ? g_xp6[(size_t)gr * 6 + j] : 0.f;
    }
    __syncthreads();

    FragC acc[2][2];
    #pragma unroll
    for (int i = 0; i < 2; i++)
        #pragma unroll
        for (int j = 0; j < 2; j++) wmma::fill_fragment(acc[i][j], 0.f);

    for (int k0 = 0; k0 < 256; k0 += 32) {
        #pragma unroll
        for (int i = 0; i < 16; i++) {             // 4096 scalar elems
            int idx = tid + i * 256;
            int m = idx >> 5, kk = idx & 31;
            int gk = k0 + kk;
            float v = be1[gk];
            #pragma unroll
            for (int j = 0; j < 6; j++) v += Xs[m][j] * We1[j * 256 + gk];
            u.s.As[m][kk] = wmma::__float_to_tf32(fmaxf(v, 0.f));
        }
        #pragma unroll
        for (int i = 0; i < 2; i++) {
            int idx = tid + i * 256;
            int r = idx >> 4, c4 = idx & 15;
            float4 v = *(const float4*)&We2[(size_t)(k0 + r) * 512 + col0 + c4*4];
            *(float4*)&u.s.Bs[r][c4*4] = tf32_4(v);
        }
        __syncthreads();
        wmma_chunk(u.s.As, u.s.Bs, warp_m, warp_n, acc);
        __syncthreads();
    }

    // stage C tile to smem, then scatter with vector reductions
    #pragma unroll
    for (int i = 0; i < 2; i++)
        #pragma unroll
        for (int j = 0; j < 2; j++)
            wmma::store_matrix_sync(&u.Cs[warp_m*32 + i*16][warp_n*32 + j*16],
                                    acc[i][j], BNP, wmma::mem_row_major);
    __syncthreads();

    int r = tid >> 1, half = tid & 1;
    int gr = row0 + r;
    if (gr < EE) {
        int s = ei[gr], d = ei[EE + gr];
        float* Lp = &g_leftsum [(size_t)s * 512 + col0];
        float* Rp = &g_rightsum[(size_t)d * 512 + col0];
        #pragma unroll
        for (int c4 = 0; c4 < 8; c4++) {
            int col = half * 32 + c4 * 4;
            float4 v  = *(float4*)&u.Cs[r][col];
            float4 bb = *(const float4*)&be2[col0 + col];
            v.x += bb.x; v.y += bb.y; v.z += bb.z; v.w += bb.w;
            red_add_v4(Lp + col, v);
            red_add_v4(Rp + col, v);
        }
    }
}

// ---- classifier GEMM; A = [out2+b2 | left*invL | right*invR] (virtual concat)
__global__ __launch_bounds__(256)
void wmma_classifier(const float* __restrict__ b2, const float* __restrict__ Wc1,
                     const float* __restrict__ bc1, float* __restrict__ C)
{
    __shared__ union {
        struct { float As[128][BKP]; float Bs[32][BNP]; } s;
        float Cs[128][BNP];
    } u;
    int tid = threadIdx.x;
    int wid = tid >> 5;
    int warp_m = wid & 3, warp_n = wid >> 2;
    int row0 = blockIdx.y * 128, col0 = blockIdx.x * 64;

    FragC acc[2][2];
    #pragma unroll
    for (int i = 0; i < 2; i++)
        #pragma unroll
        for (int j = 0; j < 2; j++) wmma::fill_fragment(acc[i][j], 0.f);

    for (int k0 = 0; k0 < 1536; k0 += 32) {
        int seg = k0 >> 9;                 // 0: out2+b2, 1: left*invL, 2: right*invR
        int kb  = k0 & 511;
        #pragma unroll
        for (int i = 0; i < 4; i++) {
            int idx = tid + i * 256;
            int r = idx >> 3, c4 = idx & 7;
            int gr = row0 + r, gk = kb + c4*4;
            float4 v;
            if (seg == 0) {
                v = *(const float4*)&g_out2[(size_t)gr * 512 + gk];
                float4 bb = *(const float4*)&b2[gk];
                v.x += bb.x; v.y += bb.y; v.z += bb.z; v.w += bb.w;
            } else if (seg == 1) {
                v = *(const float4*)&g_leftsum[(size_t)gr * 512 + gk];
                float s = g_invL[gr];
                v.x *= s; v.y *= s; v.z *= s; v.w *= s;
            } else {
                v = *(const float4*)&g_rightsum[(size_t)gr * 512 + gk];
                float s = g_invR[gr];
                v.x *= s; v.y *= s; v.z *= s; v.w *= s;
            }
            *(float4*)&u.s.As[r][c4*4] = tf32_4(v);
        }
        #pragma unroll
        for (int i = 0; i < 2; i++) {
            int idx = tid + i * 256;
            int r = idx >> 4, c4 = idx & 15;
            float4 v = *(const float4*)&Wc1[(size_t)(k0 + r) * 512 + col0 + c4*4];
            *(float4*)&u.s.Bs[r][c4*4] = tf32_4(v);
        }
        __syncthreads();
        wmma_chunk(u.s.As, u.s.Bs, warp_m, warp_n, acc);
        __syncthreads();
    }

    #pragma unroll
    for (int i = 0; i < 2; i++)
        #pragma unroll
        for (int j = 0; j < 2; j++)
            wmma::store_matrix_sync(&u.Cs[warp_m*32 + i*16][warp_n*32 + j*16],
                                    acc[i][j], BNP, wmma::mem_row_major);
    __syncthreads();

    int r = tid >> 1, half = tid & 1;
    int gr = row0 + r;
    #pragma unroll
    for (int c = 0; c < 32; c++) {
        int col = half * 32 + c;
        C[(size_t)gr * 512 + col0 + col] = fmaxf(u.Cs[r][col] + bc1[col0 + col], 0.f);
    }
}

// ---------------- fp32 fallback GEMM (small output GEMM) ----------------
template<int ACT>
__global__ __launch_bounds__(256)
void gemm64(const float* __restrict__ A, const float* __restrict__ B,
            const float* __restrict__ bias, float* __restrict__ C,
            int M, int Nc, int K)
{
    __shared__ float As[16][65];
    __shared__ float Bs[16][65];
    int tid = threadIdx.x;
    int tx = tid & 15, ty = tid >> 4;
    int row0 = blockIdx.y * 64, col0 = blockIdx.x * 64;
    float acc[4][4] = {};
    for (int k0 = 0; k0 < K; k0 += 16) {
        #pragma unroll
        for (int i = 0; i < 4; i++) {
            int idx = tid + i * 256;
            int m = idx >> 4, kk = idx & 15;
            int gr = row0 + m;
            As[kk][m] = (gr < M) ? A[(size_t)gr * K + k0 + kk] : 0.f;
        }
        #pragma unroll
        for (int i = 0; i < 4; i++) {
            int idx = tid + i * 256;
            int kk = idx >> 6, n = idx & 63;
            int gc = col0 + n;
            Bs[kk][n] = (gc < Nc) ? B[(size_t)(k0 + kk) * Nc + gc] : 0.f;
        }
        __syncthreads();
        #pragma unroll
        for (int kk = 0; kk < 16; kk++) {
            float a[4], b[4];
            #pragma unroll
            for (int i = 0; i < 4; i++) a[i] = As[kk][ty + 16*i];
            #pragma unroll
            for (int j = 0; j < 4; j++) b[j] = Bs[kk][tx + 16*j];
            #pragma unroll
            for (int i = 0; i < 4; i++)
                #pragma unroll
                for (int j = 0; j < 4; j++) acc[i][j] += a[i] * b[j];
        }
        __syncthreads();
    }
    #pragma unroll
    for (int i = 0; i < 4; i++) {
        int r = row0 + ty + 16*i;
        if (r >= M) continue;
        #pragma unroll
        for (int j = 0; j < 4; j++) {
            int c = col0 + tx + 16*j;
            if (c >= Nc) continue;
            float v = acc[i][j];
            if (bias) v += bias[c];
            if (ACT == 1) v = fmaxf(v, 0.f);
            C[(size_t)r * Nc + c] = v;
        }
    }
}

// ---------------- GAT attention dots ----------------
__global__ void att_dots_h8(const float* __restrict__ xl,
                            const float* __restrict__ asrc,
                            const float* __restrict__ adst)
{
    int w = (blockIdx.x * blockDim.x + threadIdx.x) >> 5;
    int lane = threadIdx.x & 31;
    if (w >= NN * HH) return;
    int n = w >> 3, h = w & 7;
    const float* xp = xl + (size_t)n * 512 + h * 64;
    const float* as = asrc + h * 64;
    const float* ad = adst + h * 64;
    float s = 0.f, d = 0.f;
    #pragma unroll
    for (int c = lane; c < 64; c += 32) { float v = xp[c]; s += v * as[c]; d += v * ad[c]; }
    #pragma unroll
    for (int o = 16; o; o >>= 1) { s += __shfl_down_sync(~0u, s, o); d += __shfl_down_sync(~0u, d, o); }
    if (!lane) { g_s1[w] = s; g_d1[w] = d; }
}

__global__ void att_dots_h1(const float* __restrict__ xl,
                            const float* __restrict__ asrc,
                            const float* __restrict__ adst)
{
    int n = (blockIdx.x * blockDim.x + threadIdx.x) >> 5;
    int lane = threadIdx.x & 31;
    if (n >= NN) return;
    const float* xp = xl + (size_t)n * 512;
    float s = 0.f, d = 0.f;
    #pragma unroll
    for (int c = lane; c < 512; c += 32) { float v = xp[c]; s += v * asrc[c]; d += v * adst[c]; }
    #pragma unroll
    for (int o = 16; o; o >>= 1) { s += __shfl_down_sync(~0u, s, o); d += __shfl_down_sync(~0u, d, o); }
    if (!lane) { g_s2[n] = s; g_d2[n] = d; }
}

// ---------------- segment softmax ----------------
__global__ void alpha_p1(const float* __restrict__ sarr, const float* __restrict__ darr,
                         const int* __restrict__ ei, float* __restrict__ alpha,
                         unsigned* __restrict__ amax, int Hh)
{
    int e = blockIdx.x * blockDim.x + threadIdx.x;
    if (e >= EEE) return;
    int s, d; edsd(ei, e, s, d);
    for (int h = 0; h < Hh; h++) {
        float a = sarr[s * Hh + h] + darr[d * Hh + h];
        a = (a > 0.f) ? a : 0.2f * a;
        alpha[(size_t)e * Hh + h] = a;
        atomicMax(&amax[d * Hh + h], enc_f(a));
    }
}

__global__ void alpha_p2(const int* __restrict__ ei, float* __restrict__ alpha,
                         const unsigned* __restrict__ amax, float* __restrict__ den, int Hh)
{
    int e = blockIdx.x * blockDim.x + threadIdx.x;
    if (e >= EEE) return;
    int s, d; edsd(ei, e, s, d);
    for (int h = 0; h < Hh; h++) {
        float m = dec_f(amax[d * Hh + h]);
        float ex = expf(alpha[(size_t)e * Hh + h] - m);
        alpha[(size_t)e * Hh + h] = ex;
        atomicAdd(&den[d * Hh + h], ex);
    }
}

__global__ void gat_aggregate(const float* __restrict__ alpha, const float* __restrict__ den,
                              const float* __restrict__ xl, float* __restrict__ out,
                              const int* __restrict__ ei, int Hh)
{
    int t = blockIdx.x * blockDim.x + threadIdx.x;
    if (t >= EEE * 128) return;
    int e = t >> 7, q = t & 127;
    int s, d; edsd(ei, e, s, d);
    int h = (Hh == 8) ? (q >> 4) : 0;
    float ex = alpha[(size_t)e * Hh + h];
    float w  = ex / (den[d * Hh + h] + 1e-16f);
    int c = q * 4;
    float4 v = *(const float4*)(xl + (size_t)s * 512 + c);
    v.x *= w; v.y *= w; v.z *= w; v.w *= w;
    red_add_v4(out + (size_t)d * 512 + c, v);
}

__global__ void elu_bias(float* __restrict__ x, const float* __restrict__ b) {
    int i = blockIdx.x * blockDim.x + threadIdx.x;
    if (i >= NN * 512) return;
    float v = x[i] + b[i & 511];
    x[i] = (v > 0.f) ? v : expm1f(v);
}

// ---------------- synapse point branch ----------------
__global__ void point_max(const float* __restrict__ syn) {
    int e = blockIdx.x * blockDim.x + threadIdx.x;
    if (e >= EE) return;
    const float* p = syn + (size_t)e * PTSN * 6;
    #pragma unroll
    for (int j = 0; j < 6; j++) {
        float m = p[j];
        m = fmaxf(m, p[6  + j]);
        m = fmaxf(m, p[12 + j]);
        m = fmaxf(m, p[18 + j]);
        g_xp6[(size_t)e * 6 + j] = m;
    }
}

__global__ void count_deg(const int* __restrict__ ei) {
    int e = blockIdx.x * blockDim.x + threadIdx.x;
    if (e >= EE) return;
    atomicAdd(&g_cntL[ei[e]], 1.f);
    atomicAdd(&g_cntR[ei[EE + e]], 1.f);
}

__global__ void inv_counts() {
    int n = blockIdx.x * blockDim.x + threadIdx.x;
    if (n >= NN) return;
    g_invL[n] = 1.f / fmaxf(g_cntL[n], 1.f);
    g_invR[n] = 1.f / fmaxf(g_cntR[n], 1.f);
}

// ---------------- driver ----------------
extern "C" void kernel_launch(void* const* d_in, const int* in_sizes, int n_in,
                              void* d_out, int out_size)
{
    const int*   ei       = (const int*)  d_in[0];
    const float* synapse  = (const float*)d_in[2];
    const float* x_param  = (const float*)d_in[5];
    const float* W1       = (const float*)d_in[6];
    const float* att_src1 = (const float*)d_in[7];
    const float* att_dst1 = (const float*)d_in[8];
    const float* b1       = (const float*)d_in[9];
    const float* W2       = (const float*)d_in[10];
    const float* att_src2 = (const float*)d_in[11];
    const float* att_dst2 = (const float*)d_in[12];
    const float* b2       = (const float*)d_in[13];
    const float* We1      = (const float*)d_in[14];
    const float* be1      = (const float*)d_in[15];
    const float* We2      = (const float*)d_in[16];
    const float* be2      = (const float*)d_in[17];
    const float* Wc1      = (const float*)d_in[18];
    const float* bc1      = (const float*)d_in[19];
    const float* Wc2      = (const float*)d_in[20];
    const float* bc2      = (const float*)d_in[21];
    float* out = (float*)d_out;

    float* p_poolA  = nullptr; cudaGetSymbolAddress((void**)&p_poolA,  g_poolA);
    float* p_out1   = nullptr; cudaGetSymbolAddress((void**)&p_out1,   g_out1);
    float* p_xl2    = nullptr; cudaGetSymbolAddress((void**)&p_xl2,    g_xl2);
    float* p_out2   = nullptr; cudaGetSymbolAddress((void**)&p_out2,   g_out2);
    float* p_a1     = nullptr; cudaGetSymbolAddress((void**)&p_a1,     g_alpha1);
    float* p_a2     = nullptr; cudaGetSymbolAddress((void**)&p_a2,     g_alpha2);
    unsigned* p_am1 = nullptr; cudaGetSymbolAddress((void**)&p_am1,    g_amax1);
    unsigned* p_am2 = nullptr; cudaGetSymbolAddress((void**)&p_am2,    g_amax2);
    float* p_den1   = nullptr; cudaGetSymbolAddress((void**)&p_den1,   g_den1);
    float* p_den2   = nullptr; cudaGetSymbolAddress((void**)&p_den2,   g_den2);
    float* p_s1     = nullptr; cudaGetSymbolAddress((void**)&p_s1,     g_s1);
    float* p_d1     = nullptr; cudaGetSymbolAddress((void**)&p_d1,     g_d1);
    float* p_s2     = nullptr; cudaGetSymbolAddress((void**)&p_s2,     g_s2);
    float* p_d2     = nullptr; cudaGetSymbolAddress((void**)&p_d2,     g_d2);

    float* p_xl1    = p_poolA;   // live only during GAT layer 1
    float* p_finalh = p_poolA;   // reused for classifier hidden (xl1 dead)

    // launch order: synapse branch first so the ncu capture slot (global
    // launch #6 = our 4th kernel) lands on wmma_edge_scatter
    zero_kernel<<<(NN*512 + 255) / 256, 256>>>();                                  // 1
    point_max<<<(EE + 255)/256, 256>>>(synapse);                                   // 2
    count_deg<<<(EE + 255)/256, 256>>>(ei);                                        // 3
    wmma_edge_scatter<<<dim3(512/64, (EE + 127)/128), 256>>>(We1, be1, We2, be2, ei); // 4 <- profiled
    inv_counts<<<(NN + 255)/256, 256>>>();                                         // 5

    // ---- GAT layer 1 (tf32 wmma, guarded A rows) ----
    wmma_gemm_direct<true><<<dim3(512/64, NNP/128), 256>>>(x_param, W1, p_xl1, 512, FF, NN);
    att_dots_h8<<<(NN*HH*32 + 255)/256, 256>>>(p_xl1, att_src1, att_dst1);
    alpha_p1<<<(EEE + 255)/256, 256>>>(p_s1, p_d1, ei, p_a1, p_am1, HH);
    alpha_p2<<<(EEE + 255)/256, 256>>>(ei, p_a1, p_am1, p_den1, HH);
    gat_aggregate<<<(EEE*128 + 255)/256, 256>>>(p_a1, p_den1, p_xl1, p_out1, ei, HH);
    elu_bias<<<(NN*512 + 255)/256, 256>>>(p_out1, b1);

    // ---- GAT layer 2 (tf32 wmma) ----
    wmma_gemm_direct<false><<<dim3(512/64, NNP/128), 256>>>(p_out1, W2, p_xl2, 512, 512, NNP);
    att_dots_h1<<<(NN*32 + 255)/256, 256>>>(p_xl2, att_src2, att_dst2);
    alpha_p1<<<(EEE + 255)/256, 256>>>(p_s2, p_d2, ei, p_a2, p_am2, 1);
    alpha_p2<<<(EEE + 255)/256, 256>>>(ei, p_a2, p_am2, p_den2, 1);
    gat_aggregate<<<(EEE*128 + 255)/256, 256>>>(p_a2, p_den2, p_xl2, p_out2, ei, 1);

    // ---- classifier (tf32 wmma, virtual concat A) ----
    wmma_classifier<<<dim3(512/64, NNP/128), 256>>>(b2, Wc1, bc1, p_finalh);
    gemm64<0><<<dim3((NCLSC + 63)/64, (NN + 63)/64), 256>>>(p_finalh, Wc2, bc2, out, NN, NCLSC, 512);
}

// round 13
// speedup vs baseline: 3.2323x; 1.7122x over previous
#include <cuda_runtime.h>
#include <cuda_bf16.h>
#include <mma.h>
#include <math.h>

using namespace nvcuda;

// ---------------- problem constants ----------------
#define NN   20000
#define NNP  20096          // 157*128, padded node count for guard-free wmma tiles
#define FF   128
#define HH   8
#define EE   200000
#define PTSN 4
#define EEE  (EE+NN)
#define NCLSC 133

// ---------------- scratch (device globals; zero-initialized at load) -------
__device__ float    g_poolA[(size_t)NNP*512];   // xl1 (layer1) then finalh
__device__ float    g_s1[NN*HH];
__device__ float    g_d1[NN*HH];
__device__ unsigned g_amax1[NN*HH];
__device__ float    g_den1[NN*HH];
__device__ float    g_alpha1[(size_t)EEE*HH];
__device__ float    g_out1[(size_t)NNP*512];
__device__ float    g_xl2[(size_t)NNP*512];
__device__ float    g_s2[NN];
__device__ float    g_d2[NN];
__device__ unsigned g_amax2[NN];
__device__ float    g_den2[NN];
__device__ float    g_alpha2[EEE];
__device__ float    g_out2[(size_t)NNP*512];
__device__ float    g_xp6[EE*6];
__device__ float    g_leftH [(size_t)NNP*256];  // scatter-mean of relu(h1), 256-dim
__device__ float    g_rightH[(size_t)NNP*256];
__device__ float    g_Wfold[512*512];           // [We2@Wc1_b ; We2@Wc1_c]
__device__ float    g_vb[512];                  // be2 @ Wc1_b
__device__ float    g_vc[512];                  // be2 @ Wc1_c
__device__ float    g_invL[NNP];
__device__ float    g_invR[NNP];
__device__ float    g_hasL[NNP];
__device__ float    g_hasR[NNP];
__device__ float    g_cntL[NN];
__device__ float    g_cntR[NN];

// ---------------- helpers ----------------
__device__ __forceinline__ unsigned enc_f(float f) {
    unsigned u = __float_as_uint(f);
    return (u & 0x80000000u) ? ~u : (u | 0x80000000u);
}
__device__ __forceinline__ float dec_f(unsigned u) {
    return (u & 0x80000000u) ? __uint_as_float(u & 0x7FFFFFFFu)
                             : __uint_as_float(~u);
}
__device__ __forceinline__ void edsd(const int* __restrict__ ei, int e, int& s, int& d) {
    if (e < EE) { s = ei[e]; d = ei[EE + e]; }
    else        { s = d = e - EE; }
}
__device__ __forceinline__ void red_add_v4(float* p, float4 v) {
    asm volatile("red.global.add.v4.f32 [%0], {%1,%2,%3,%4};"
                 :: "l"(p), "f"(v.x), "f"(v.y), "f"(v.z), "f"(v.w) : "memory");
}

// ---------------- zero/init ----------------
__global__ void zero_kernel() {
    int i = blockIdx.x * blockDim.x + threadIdx.x;
    if (i < NN*512) { g_out1[i] = 0.f; g_out2[i] = 0.f; }
    if (i < NN*256) { g_leftH[i] = 0.f; g_rightH[i] = 0.f; }
    if (i < NN*HH)  { g_amax1[i] = 0u; g_den1[i] = 0.f; }
    if (i < NN)     { g_amax2[i] = 0u; g_den2[i] = 0.f; g_cntL[i] = 0.f; g_cntR[i] = 0.f; }
}

// ================= tf32 wmma GEMM framework =================
#define BKP 40
#define BNP 72

typedef wmma::fragment<wmma::matrix_a, 16, 16, 8, wmma::precision::tf32, wmma::row_major> FragA;
typedef wmma::fragment<wmma::matrix_b, 16, 16, 8, wmma::precision::tf32, wmma::row_major> FragB;
typedef wmma::fragment<wmma::accumulator, 16, 16, 8, float> FragC;

__device__ __forceinline__ float4 tf32_4(float4 v) {
    v.x = wmma::__float_to_tf32(v.x); v.y = wmma::__float_to_tf32(v.y);
    v.z = wmma::__float_to_tf32(v.z); v.w = wmma::__float_to_tf32(v.w);
    return v;
}

__device__ __forceinline__ void wmma_chunk(
    const float (*As)[BKP], const float (*Bs)[BNP],
    int warp_m, int warp_n, FragC acc[2][2])
{
    #pragma unroll
    for (int ks = 0; ks < 4; ks++) {
        FragA a[2]; FragB b[2];
        #pragma unroll
        for (int i = 0; i < 2; i++)
            wmma::load_matrix_sync(a[i], &As[warp_m*32 + i*16][ks*8], BKP);
        #pragma unroll
        for (int j = 0; j < 2; j++)
            wmma::load_matrix_sync(b[j], &Bs[ks*8][warp_n*32 + j*16], BNP);
        #pragma unroll
        for (int i = 0; i < 2; i++)
            #pragma unroll
            for (int j = 0; j < 2; j++)
                wmma::mma_sync(acc[i][j], a[i], b[j], acc[i][j]);
    }
}

// ---- plain wmma GEMM, direct store. GUARD: clamp A rows >= Mreal to zero.
template<bool GUARD>
__global__ __launch_bounds__(256)
void wmma_gemm_direct(const float* __restrict__ A, const float* __restrict__ B,
                      float* __restrict__ C, int Nc, int K, int Mreal)
{
    __shared__ float As[128][BKP];
    __shared__ float Bs[32][BNP];
    int tid = threadIdx.x;
    int wid = tid >> 5;
    int warp_m = wid & 3, warp_n = wid >> 2;
    int row0 = blockIdx.y * 128, col0 = blockIdx.x * 64;
    FragC acc[2][2];
    #pragma unroll
    for (int i = 0; i < 2; i++)
        #pragma unroll
        for (int j = 0; j < 2; j++) wmma::fill_fragment(acc[i][j], 0.f);

    for (int k0 = 0; k0 < K; k0 += 32) {
        #pragma unroll
        for (int i = 0; i < 4; i++) {
            int idx = tid + i * 256;
            int r = idx >> 3, c4 = idx & 7;
            float4 v = make_float4(0.f, 0.f, 0.f, 0.f);
            if (!GUARD || (row0 + r) < Mreal)
                v = *(const float4*)&A[(size_t)(row0 + r) * K + k0 + c4*4];
            *(float4*)&As[r][c4*4] = tf32_4(v);
        }
        #pragma unroll
        for (int i = 0; i < 2; i++) {
            int idx = tid + i * 256;
            int r = idx >> 4, c4 = idx & 15;
            float4 v = *(const float4*)&B[(size_t)(k0 + r) * Nc + col0 + c4*4];
            *(float4*)&Bs[r][c4*4] = tf32_4(v);
        }
        __syncthreads();
        wmma_chunk(As, Bs, warp_m, warp_n, acc);
        __syncthreads();
    }
    #pragma unroll
    for (int i = 0; i < 2; i++)
        #pragma unroll
        for (int j = 0; j < 2; j++)
            wmma::store_matrix_sync(
                &C[(size_t)(row0 + warp_m*32 + i*16) * Nc + col0 + warp_n*32 + j*16],
                acc[i][j], Nc, wmma::mem_row_major);
}

// ---- edge branch: h1 = relu(xp6 @ We1 + be1) per edge; scatter-add 256-dim
//      into leftH[src], rightH[dst]. One warp per edge slice; weights in regs.
__global__ __launch_bounds__(256)
void edge_mlp_scatter(const float* __restrict__ We1, const float* __restrict__ be1,
                      const int* __restrict__ ei)
{
    int lane = threadIdx.x & 31;
    int warp = (blockIdx.x << 3) + (threadIdx.x >> 5);
    int nwarps = gridDim.x << 3;
    int ch0 = lane * 8;

    float w[6][8], b[8];
    #pragma unroll
    for (int j = 0; j < 6; j++)
        #pragma unroll
        for (int k = 0; k < 8; k++) w[j][k] = We1[j * 256 + ch0 + k];
    #pragma unroll
    for (int k = 0; k < 8; k++) b[k] = be1[ch0 + k];

    for (int e = warp; e < EE; e += nwarps) {
        float xv = (lane < 6) ? g_xp6[(size_t)e * 6 + lane] : 0.f;
        float x0 = __shfl_sync(~0u, xv, 0);
        float x1 = __shfl_sync(~0u, xv, 1);
        float x2 = __shfl_sync(~0u, xv, 2);
        float x3 = __shfl_sync(~0u, xv, 3);
        float x4 = __shfl_sync(~0u, xv, 4);
        float x5 = __shfl_sync(~0u, xv, 5);
        int sv = (lane < 2) ? ei[e + lane * EE] : 0;
        int s = __shfl_sync(~0u, sv, 0);
        int d = __shfl_sync(~0u, sv, 1);

        float h[8];
        #pragma unroll
        for (int k = 0; k < 8; k++) {
            float v = b[k];
            v += x0 * w[0][k]; v += x1 * w[1][k]; v += x2 * w[2][k];
            v += x3 * w[3][k]; v += x4 * w[4][k]; v += x5 * w[5][k];
            h[k] = fmaxf(v, 0.f);
        }
        float4 v0 = make_float4(h[0], h[1], h[2], h[3]);
        float4 v1 = make_float4(h[4], h[5], h[6], h[7]);
        red_add_v4(&g_leftH [(size_t)s * 256 + ch0],     v0);
        red_add_v4(&g_leftH [(size_t)s * 256 + ch0 + 4], v1);
        red_add_v4(&g_rightH[(size_t)d * 256 + ch0],     v0);
        red_add_v4(&g_rightH[(size_t)d * 256 + ch0 + 4], v1);
    }
}

// ---- classifier GEMM, K=1024; A = [out2+b2 | meanHL | meanHR] virtual;
//      B = [Wc1_a rows | Wfold rows]; bias = bc1 + hasL*vb + hasR*vc; relu.
__global__ __launch_bounds__(256)
void wmma_classifier(const float* __restrict__ b2, const float* __restrict__ Wc1,
                     const float* __restrict__ bc1, float* __restrict__ C)
{
    __shared__ union {
        struct { float As[128][BKP]; float Bs[32][BNP]; } s;
        float Cs[128][BNP];
    } u;
    int tid = threadIdx.x;
    int wid = tid >> 5;
    int warp_m = wid & 3, warp_n = wid >> 2;
    int row0 = blockIdx.y * 128, col0 = blockIdx.x * 64;

    FragC acc[2][2];
    #pragma unroll
    for (int i = 0; i < 2; i++)
        #pragma unroll
        for (int j = 0; j < 2; j++) wmma::fill_fragment(acc[i][j], 0.f);

    for (int k0 = 0; k0 < 1024; k0 += 32) {
        #pragma unroll
        for (int i = 0; i < 4; i++) {
            int idx = tid + i * 256;
            int r = idx >> 3, c4 = idx & 7;
            int gr = row0 + r;
            float4 v;
            if (k0 < 512) {
                int gk = k0 + c4*4;
                v = *(const float4*)&g_out2[(size_t)gr * 512 + gk];
                float4 bb = *(const float4*)&b2[gk];
                v.x += bb.x; v.y += bb.y; v.z += bb.z; v.w += bb.w;
            } else if (k0 < 768) {
                int gk = (k0 - 512) + c4*4;
                v = *(const float4*)&g_leftH[(size_t)gr * 256 + gk];
                float sc = g_invL[gr];
                v.x *= sc; v.y *= sc; v.z *= sc; v.w *= sc;
            } else {
                int gk = (k0 - 768) + c4*4;
                v = *(const float4*)&g_rightH[(size_t)gr * 256 + gk];
                float sc = g_invR[gr];
                v.x *= sc; v.y *= sc; v.z *= sc; v.w *= sc;
            }
            *(float4*)&u.s.As[r][c4*4] = tf32_4(v);
        }
        #pragma unroll
        for (int i = 0; i < 2; i++) {
            int idx = tid + i * 256;
            int r = idx >> 4, c4 = idx & 15;
            const float* src = (k0 < 512)
                ? &Wc1[(size_t)(k0 + r) * 512 + col0 + c4*4]
                : &g_Wfold[(size_t)(k0 - 512 + r) * 512 + col0 + c4*4];
            *(float4*)&u.s.Bs[r][c4*4] = tf32_4(*(const float4*)src);
        }
        __syncthreads();
        wmma_chunk(u.s.As, u.s.Bs, warp_m, warp_n, acc);
        __syncthreads();
    }

    #pragma unroll
    for (int i = 0; i < 2; i++)
        #pragma unroll
        for (int j = 0; j < 2; j++)
            wmma::store_matrix_sync(&u.Cs[warp_m*32 + i*16][warp_n*32 + j*16],
                                    acc[i][j], BNP, wmma::mem_row_major);
    __syncthreads();

    int r = tid >> 1, half = tid & 1;
    int gr = row0 + r;
    float hl = g_hasL[gr], hr = g_hasR[gr];
    #pragma unroll
    for (int c = 0; c < 32; c++) {
        int col = col0 + half * 32 + c;
        float v = u.Cs[r][half * 32 + c] + bc1[col] + hl * g_vb[col] + hr * g_vc[col];
        C[(size_t)gr * 512 + col] = fmaxf(v, 0.f);
    }
}

// ---------------- fp32 GEMM (fold + output head) ----------------
template<int ACT>
__global__ __launch_bounds__(256)
void gemm64(const float* __restrict__ A, const float* __restrict__ B,
            const float* __restrict__ bias, float* __restrict__ C,
            int M, int Nc, int K)
{
    __shared__ float As[16][65];
    __shared__ float Bs[16][65];
    int tid = threadIdx.x;
    int tx = tid & 15, ty = tid >> 4;
    int row0 = blockIdx.y * 64, col0 = blockIdx.x * 64;
    float acc[4][4] = {};
    for (int k0 = 0; k0 < K; k0 += 16) {
        #pragma unroll
        for (int i = 0; i < 4; i++) {
            int idx = tid + i * 256;
            int m = idx >> 4, kk = idx & 15;
            int gr = row0 + m;
            As[kk][m] = (gr < M) ? A[(size_t)gr * K + k0 + kk] : 0.f;
        }
        #pragma unroll
        for (int i = 0; i < 4; i++) {
            int idx = tid + i * 256;
            int kk = idx >> 6, n = idx & 63;
            int gc = col0 + n;
            Bs[kk][n] = (gc < Nc) ? B[(size_t)(k0 + kk) * Nc + gc] : 0.f;
        }
        __syncthreads();
        #pragma unroll
        for (int kk = 0; kk < 16; kk++) {
            float a[4], b[4];
            #pragma unroll
            for (int i = 0; i < 4; i++) a[i] = As[kk][ty + 16*i];
            #pragma unroll
            for (int j = 0; j < 4; j++) b[j] = Bs[kk][tx + 16*j];
            #pragma unroll
            for (int i = 0; i < 4; i++)
                #pragma unroll
                for (int j = 0; j < 4; j++) acc[i][j] += a[i] * b[j];
        }
        __syncthreads();
    }
    #pragma unroll
    for (int i = 0; i < 4; i++) {
        int r = row0 + ty + 16*i;
        if (r >= M) continue;
        #pragma unroll
        for (int j = 0; j < 4; j++) {
            int c = col0 + tx + 16*j;
            if (c >= Nc) continue;
            float v = acc[i][j];
            if (bias) v += bias[c];
            if (ACT == 1) v = fmaxf(v, 0.f);
            C[(size_t)r * Nc + c] = v;
        }
    }
}

// vb = be2 @ Wc1[512:1024], vc = be2 @ Wc1[1024:1536]
__global__ void fold_bias(const float* __restrict__ be2, const float* __restrict__ Wc1) {
    int c = blockIdx.x * blockDim.x + threadIdx.x;
    if (c >= 512) return;
    float a = 0.f, b = 0.f;
    for (int k = 0; k < 512; k++) {
        float w = be2[k];
        a += w * Wc1[(size_t)(512  + k) * 512 + c];
        b += w * Wc1[(size_t)(1024 + k) * 512 + c];
    }
    g_vb[c] = a; g_vc[c] = b;
}

// ---------------- GAT attention dots ----------------
__global__ void att_dots_h8(const float* __restrict__ xl,
                            const float* __restrict__ asrc,
                            const float* __restrict__ adst)
{
    int w = (blockIdx.x * blockDim.x + threadIdx.x) >> 5;
    int lane = threadIdx.x & 31;
    if (w >= NN * HH) return;
    int n = w >> 3, h = w & 7;
    const float* xp = xl + (size_t)n * 512 + h * 64;
    const float* as = asrc + h * 64;
    const float* ad = adst + h * 64;
    float s = 0.f, d = 0.f;
    #pragma unroll
    for (int c = lane; c < 64; c += 32) { float v = xp[c]; s += v * as[c]; d += v * ad[c]; }
    #pragma unroll
    for (int o = 16; o; o >>= 1) { s += __shfl_down_sync(~0u, s, o); d += __shfl_down_sync(~0u, d, o); }
    if (!lane) { g_s1[w] = s; g_d1[w] = d; }
}

__global__ void att_dots_h1(const float* __restrict__ xl,
                            const float* __restrict__ asrc,
                            const float* __restrict__ adst)
{
    int n = (blockIdx.x * blockDim.x + threadIdx.x) >> 5;
    int lane = threadIdx.x & 31;
    if (n >= NN) return;
    const float* xp = xl + (size_t)n * 512;
    float s = 0.f, d = 0.f;
    #pragma unroll
    for (int c = lane; c < 512; c += 32) { float v = xp[c]; s += v * asrc[c]; d += v * adst[c]; }
    #pragma unroll
    for (int o = 16; o; o >>= 1) { s += __shfl_down_sync(~0u, s, o); d += __shfl_down_sync(~0u, d, o); }
    if (!lane) { g_s2[n] = s; g_d2[n] = d; }
}

// ---------------- segment softmax ----------------
__global__ void alpha_p1(const float* __restrict__ sarr, const float* __restrict__ darr,
                         const int* __restrict__ ei, float* __restrict__ alpha,
                         unsigned* __restrict__ amax, int Hh)
{
    int e = blockIdx.x * blockDim.x + threadIdx.x;
    if (e >= EEE) return;
    int s, d; edsd(ei, e, s, d);
    for (int h = 0; h < Hh; h++) {
        float a = sarr[s * Hh + h] + darr[d * Hh + h];
        a = (a > 0.f) ? a : 0.2f * a;
        alpha[(size_t)e * Hh + h] = a;
        atomicMax(&amax[d * Hh + h], enc_f(a));
    }
}

__global__ void alpha_p2(const int* __restrict__ ei, float* __restrict__ alpha,
                         const unsigned* __restrict__ amax, float* __restrict__ den, int Hh)
{
    int e = blockIdx.x * blockDim.x + threadIdx.x;
    if (e >= EEE) return;
    int s, d; edsd(ei, e, s, d);
    for (int h = 0; h < Hh; h++) {
        float m = dec_f(amax[d * Hh + h]);
        float ex = expf(alpha[(size_t)e * Hh + h] - m);
        alpha[(size_t)e * Hh + h] = ex;
        atomicAdd(&den[d * Hh + h], ex);
    }
}

__global__ void gat_aggregate(const float* __restrict__ alpha, const float* __restrict__ den,
                              const float* __restrict__ xl, float* __restrict__ out,
                              const int* __restrict__ ei, int Hh)
{
    int t = blockIdx.x * blockDim.x + threadIdx.x;
    if (t >= EEE * 128) return;
    int e = t >> 7, q = t & 127;
    int s, d; edsd(ei, e, s, d);
    int h = (Hh == 8) ? (q >> 4) : 0;
    float ex = alpha[(size_t)e * Hh + h];
    float w  = ex / (den[d * Hh + h] + 1e-16f);
    int c = q * 4;
    float4 v = *(const float4*)(xl + (size_t)s * 512 + c);
    v.x *= w; v.y *= w; v.z *= w; v.w *= w;
    red_add_v4(out + (size_t)d * 512 + c, v);
}

__global__ void elu_bias(float* __restrict__ x, const float* __restrict__ b) {
    int i = blockIdx.x * blockDim.x + threadIdx.x;
    if (i >= NN * 512) return;
    float v = x[i] + b[i & 511];
    x[i] = (v > 0.f) ? v : expm1f(v);
}

// ---------------- synapse point branch ----------------
__global__ void point_max(const float* __restrict__ syn) {
    int e = blockIdx.x * blockDim.x + threadIdx.x;
    if (e >= EE) return;
    const float* p = syn + (size_t)e * PTSN * 6;
    #pragma unroll
    for (int j = 0; j < 6; j++) {
        float m = p[j];
        m = fmaxf(m, p[6  + j]);
        m = fmaxf(m, p[12 + j]);
        m = fmaxf(m, p[18 + j]);
        g_xp6[(size_t)e * 6 + j] = m;
    }
}

__global__ void count_deg(const int* __restrict__ ei) {
    int e = blockIdx.x * blockDim.x + threadIdx.x;
    if (e >= EE) return;
    atomicAdd(&g_cntL[ei[e]], 1.f);
    atomicAdd(&g_cntR[ei[EE + e]], 1.f);
}

__global__ void inv_counts() {
    int n = blockIdx.x * blockDim.x + threadIdx.x;
    if (n >= NN) return;
    float cl = g_cntL[n], cr = g_cntR[n];
    g_invL[n] = 1.f / fmaxf(cl, 1.f);
    g_invR[n] = 1.f / fmaxf(cr, 1.f);
    g_hasL[n] = (cl > 0.f) ? 1.f : 0.f;
    g_hasR[n] = (cr > 0.f) ? 1.f : 0.f;
}

// ---------------- driver ----------------
extern "C" void kernel_launch(void* const* d_in, const int* in_sizes, int n_in,
                              void* d_out, int out_size)
{
    const int*   ei       = (const int*)  d_in[0];
    const float* synapse  = (const float*)d_in[2];
    const float* x_param  = (const float*)d_in[5];
    const float* W1       = (const float*)d_in[6];
    const float* att_src1 = (const float*)d_in[7];
    const float* att_dst1 = (const float*)d_in[8];
    const float* b1       = (const float*)d_in[9];
    const float* W2       = (const float*)d_in[10];
    const float* att_src2 = (const float*)d_in[11];
    const float* att_dst2 = (const float*)d_in[12];
    const float* b2       = (const float*)d_in[13];
    const float* We1      = (const float*)d_in[14];
    const float* be1      = (const float*)d_in[15];
    const float* We2      = (const float*)d_in[16];
    const float* be2      = (const float*)d_in[17];
    const float* Wc1      = (const float*)d_in[18];
    const float* bc1      = (const float*)d_in[19];
    const float* Wc2      = (const float*)d_in[20];
    const float* bc2      = (const float*)d_in[21];
    float* out = (float*)d_out;

    float* p_poolA  = nullptr; cudaGetSymbolAddress((void**)&p_poolA,  g_poolA);
    float* p_out1   = nullptr; cudaGetSymbolAddress((void**)&p_out1,   g_out1);
    float* p_xl2    = nullptr; cudaGetSymbolAddress((void**)&p_xl2,    g_xl2);
    float* p_out2   = nullptr; cudaGetSymbolAddress((void**)&p_out2,   g_out2);
    float* p_a1     = nullptr; cudaGetSymbolAddress((void**)&p_a1,     g_alpha1);
    float* p_a2     = nullptr; cudaGetSymbolAddress((void**)&p_a2,     g_alpha2);
    unsigned* p_am1 = nullptr; cudaGetSymbolAddress((void**)&p_am1,    g_amax1);
    unsigned* p_am2 = nullptr; cudaGetSymbolAddress((void**)&p_am2,    g_amax2);
    float* p_den1   = nullptr; cudaGetSymbolAddress((void**)&p_den1,   g_den1);
    float* p_den2   = nullptr; cudaGetSymbolAddress((void**)&p_den2,   g_den2);
    float* p_s1     = nullptr; cudaGetSymbolAddress((void**)&p_s1,     g_s1);
    float* p_d1     = nullptr; cudaGetSymbolAddress((void**)&p_d1,     g_d1);
    float* p_s2     = nullptr; cudaGetSymbolAddress((void**)&p_s2,     g_s2);
    float* p_d2     = nullptr; cudaGetSymbolAddress((void**)&p_d2,     g_d2);
    float* p_Wfold  = nullptr; cudaGetSymbolAddress((void**)&p_Wfold,  g_Wfold);

    float* p_xl1    = p_poolA;   // live only during GAT layer 1
    float* p_finalh = p_poolA;   // reused for classifier hidden (xl1 dead)

    // launch order: edge branch first so the ncu capture slot (our 4th
    // launch) lands on edge_mlp_scatter
    zero_kernel<<<(NN*512 + 255) / 256, 256>>>();                                  // 1
    point_max<<<(EE + 255)/256, 256>>>(synapse);                                   // 2
    count_deg<<<(EE + 255)/256, 256>>>(ei);                                        // 3
    edge_mlp_scatter<<<1024, 256>>>(We1, be1, ei);                                 // 4 <- profiled
    inv_counts<<<(NN + 255)/256, 256>>>();                                         // 5

    // ---- fold We2 into classifier weights (fp32) ----
    gemm64<0><<<dim3(8, 4), 256>>>(We2, Wc1 + (size_t)512*512,  nullptr, p_Wfold,                   256, 512, 512);
    gemm64<0><<<dim3(8, 4), 256>>>(We2, Wc1 + (size_t)1024*512, nullptr, p_Wfold + (size_t)256*512, 256, 512, 512);
    fold_bias<<<2, 256>>>(be2, Wc1);

    // ---- GAT layer 1 (tf32 wmma, guarded A rows) ----
    wmma_gemm_direct<true><<<dim3(512/64, NNP/128), 256>>>(x_param, W1, p_xl1, 512, FF, NN);
    att_dots_h8<<<(NN*HH*32 + 255)/256, 256>>>(p_xl1, att_src1, att_dst1);
    alpha_p1<<<(EEE + 255)/256, 256>>>(p_s1, p_d1, ei, p_a1, p_am1, HH);
    alpha_p2<<<(EEE + 255)/256, 256>>>(ei, p_a1, p_am1, p_den1, HH);
    gat_aggregate<<<(EEE*128 + 255)/256, 256>>>(p_a1, p_den1, p_xl1, p_out1, ei, HH);
    elu_bias<<<(NN*512 + 255)/256, 256>>>(p_out1, b1);

    // ---- GAT layer 2 (tf32 wmma) ----
    wmma_gemm_direct<false><<<dim3(512/64, NNP/128), 256>>>(p_out1, W2, p_xl2, 512, 512, NNP);
    att_dots_h1<<<(NN*32 + 255)/256, 256>>>(p_xl2, att_src2, att_dst2);
    alpha_p1<<<(EEE + 255)/256, 256>>>(p_s2, p_d2, ei, p_a2, p_am2, 1);
    alpha_p2<<<(EEE + 255)/256, 256>>>(ei, p_a2, p_am2, p_den2, 1);
    gat_aggregate<<<(EEE*128 + 255)/256, 256>>>(p_a2, p_den2, p_xl2, p_out2, ei, 1);

    // ---- classifier (tf32 wmma, K=1024 with folded edge weights) ----
    wmma_classifier<<<dim3(512/64, NNP/128), 256>>>(b2, Wc1, bc1, p_finalh);
    gemm64<0><<<dim3((NCLSC + 63)/64, (NN + 63)/64), 256>>>(p_finalh, Wc2, bc2, out, NN, NCLSC, 512);
}